// round 6
// baseline (speedup 1.0000x reference)
#include <cuda_runtime.h>
#include <math.h>

#define N_BINS 1024
#define NMASK  (N_BINS - 1)
#define DIM    512
#define DIM4   128            // DIM / 4 (float4 units)
#define NSTEPS 240
#define NK     122            // lags k in [-61, 60]
#define TI     8              // bins per block
#define NBLK   (N_BINS / TI)  // 128 blocks
#define RWIN   132            // window rows r'=0..131 (need 0..129)
#define NCHUNK 8              // K chunks of 64 floats
#define CHK4   16             // float4 per chunk per row
#define KC     8              // k-split groups
#define TG     2              // t-tile groups (4 t each)
#define RQ     33             // r-quads (each thread: rows rq, rq+33, rq+66, rq+99)
#define NACT   (KC * TG * RQ) // 528 active threads
#define NTHREADS 544          // 17 warps

// Scratch (device globals; no allocations allowed)
__device__ float g_bpart[NSTEPS * NBLK];   // per-(step, block) partial sums
__device__ unsigned g_ticket;              // last-block election (reset each launch)

__device__ __forceinline__ float dot4(float4 a, float4 b) {
    return a.x * b.x + a.y * b.y + a.z * b.z + a.w * b.w;
}
__device__ __forceinline__ float fma4(float4 p, float4 q, float acc) {
    acc = fmaf(p.x, q.x, acc);
    acc = fmaf(p.y, q.y, acc);
    acc = fmaf(p.z, q.z, acc);
    acc = fmaf(p.w, q.w, acc);
    return acc;
}

// ---------------------------------------------------------------------------
// k_main: one block per 8-bin tile i0..i0+7.
//  GEMM phase: C[t][r'] = P[i0+t] . Q[(i0-61+r') mod N] for t in [0,8), r' in
//  [0,132), register-tiled 4t x 4r, k-split 8, K streamed in 8 smem chunks.
//  Stats (Q2, A) accumulated by tg0 threads on the same smem data.
//  Epilogue: reduce kc partials -> Xs band / sQ2 / sA; evaluate 240 steps;
//  last block reduces g_bpart -> argmin -> out.
// ---------------------------------------------------------------------------
__global__ void __launch_bounds__(NTHREADS) k_main(const float* __restrict__ Dq,
                                                   const float* __restrict__ Dp,
                                                   float* __restrict__ out) {
    // smem: Ps chunk 2KB | union(Qc 33792B, Sp 8448B, Cp 33792B) | Xs 4KB | stats
    __shared__ float4 Psc[TI][CHK4];                    // P tile, current chunk
    __shared__ __align__(16) float uni[RWIN * CHK4 * 4]; // 33792 B
    __shared__ float Xs[TI][128];                        // kk = k+61 in [0,121]
    __shared__ float sQ2[RWIN], sA[RWIN], sP2[TI];
    __shared__ unsigned long long wk[NTHREADS / 32];
    __shared__ bool is_last;

    float4* Qc = (float4*)uni;                 // Qc[r*16 + ((l + r) & 15)]
    float*  Sp = uni;                          // Sp[a][kc][r] : a*KC*RWIN + kc*RWIN + r
    float*  Cp = uni;                          // Cp[kc][t][r] : kc*TI*RWIN + t*RWIN + r

    const int i0   = blockIdx.x * TI;
    const int tid  = threadIdx.x;
    const int lane = tid & 31;
    const int warp = tid >> 5;

    const bool act = (tid < NACT);
    const int  rq  = act ? (tid % RQ) : 0;
    const int  grp = act ? (tid / RQ) : 0;     // 0..15
    const int  tg  = grp & 1;                  // t-group: rows t in [4tg, 4tg+4)
    const int  kc  = grp >> 1;                 // k-split group

    const float4* P4 = (const float4*)Dp;
    const float4* Q4 = (const float4*)Dq;

    // loader roles
    const int lr = tid >> 4;                   // 0..33 (row base per pass)
    const int ll = tid & 15;                   // float4 column within chunk

    float4 pf_q[4];                            // Qc prefetch (4 passes)
    float4 pf_p;                               // Ps prefetch (tid < 128)
    float  p2acc = 0.0f;

    // ---- prefetch + store chunk 0 -------------------------------------
    {
        const int c = 0;
        #pragma unroll
        for (int p = 0; p < 4; p++) {
            int r = lr + p * 34;
            if (r < RWIN) {
                int j = (i0 - 61 + r) & NMASK;
                pf_q[p] = Q4[j * DIM4 + c * CHK4 + ll];
            }
        }
        if (tid < 128) pf_p = P4[(i0 + lr) * DIM4 + c * CHK4 + ll];
    }
    {
        #pragma unroll
        for (int p = 0; p < 4; p++) {
            int r = lr + p * 34;
            if (r < RWIN) Qc[r * CHK4 + ((ll + r) & 15)] = pf_q[p];
        }
        if (tid < 128) { Psc[lr][ll] = pf_p; p2acc += dot4(pf_p, pf_p); }
    }
    __syncthreads();

    // ---- GEMM accumulators --------------------------------------------
    float acc[4][4];                           // [tt][m]
    #pragma unroll
    for (int a = 0; a < 4; a++)
        #pragma unroll
        for (int b = 0; b < 4; b++) acc[a][b] = 0.0f;
    float q2a[4] = {0.f, 0.f, 0.f, 0.f};       // tg0 only
    float aaa[4] = {0.f, 0.f, 0.f, 0.f};       // tg0 only

    // ---- chunk loop ----------------------------------------------------
    for (int c = 0; c < NCHUNK; c++) {
        // prefetch next chunk into registers (overlaps compute)
        if (c < NCHUNK - 1) {
            const int cn = c + 1;
            #pragma unroll
            for (int p = 0; p < 4; p++) {
                int r = lr + p * 34;
                if (r < RWIN) {
                    int j = (i0 - 61 + r) & NMASK;
                    pf_q[p] = Q4[j * DIM4 + cn * CHK4 + ll];
                }
            }
            if (tid < 128) pf_p = P4[(i0 + lr) * DIM4 + cn * CHK4 + ll];
        }

        // compute this chunk: thread's k4 slots l = 2kc, 2kc+1
        if (act) {
            #pragma unroll
            for (int j2 = 0; j2 < 2; j2++) {
                const int l = 2 * kc + j2;
                float4 qv[4];
                #pragma unroll
                for (int m = 0; m < 4; m++) {
                    int r = rq + 33 * m;
                    qv[m] = Qc[r * CHK4 + ((l + r) & 15)];
                }
                float4 pv[4];
                #pragma unroll
                for (int tt = 0; tt < 4; tt++) pv[tt] = Psc[tg * 4 + tt][l];
                #pragma unroll
                for (int tt = 0; tt < 4; tt++)
                    #pragma unroll
                    for (int m = 0; m < 4; m++)
                        acc[tt][m] = fma4(pv[tt], qv[m], acc[tt][m]);
                if (tg == 0) {
                    #pragma unroll
                    for (int m = 0; m < 4; m++) {
                        int r  = rq + 33 * m;
                        int pr = (r == 0) ? 0 : (r - 1);
                        float4 pq = Qc[pr * CHK4 + ((l + pr) & 15)];
                        q2a[m] = fma4(qv[m], qv[m], q2a[m]);
                        aaa[m] = fma4(qv[m], pq,    aaa[m]);
                    }
                }
            }
        }
        __syncthreads();   // all reads of Qc done

        if (c < NCHUNK - 1) {
            #pragma unroll
            for (int p = 0; p < 4; p++) {
                int r = lr + p * 34;
                if (r < RWIN) Qc[r * CHK4 + ((ll + r) & 15)] = pf_q[p];
            }
            if (tid < 128) { Psc[lr][ll] = pf_p; p2acc += dot4(pf_p, pf_p); }
            __syncthreads();
        }
    }

    // ---- P2 reduce (16 consecutive lanes share one t) -------------------
    if (tid < 128) {
        #pragma unroll
        for (int off = 8; off; off >>= 1)
            p2acc += __shfl_xor_sync(0xffffffffu, p2acc, off);
        if (ll == 0) sP2[lr] = p2acc;
    }

    // ---- stats: write tg0 partials, reduce over kc ----------------------
    if (act && tg == 0) {
        #pragma unroll
        for (int m = 0; m < 4; m++) {
            int r = rq + 33 * m;
            Sp[0 * KC * RWIN + kc * RWIN + r] = q2a[m];
            Sp[1 * KC * RWIN + kc * RWIN + r] = aaa[m];
        }
    }
    __syncthreads();
    if (tid < 2 * RWIN) {
        int a = (tid >= RWIN) ? 1 : 0;
        int r = tid - a * RWIN;
        const float* base = Sp + a * KC * RWIN + r;
        float s = 0.f;
        #pragma unroll
        for (int k = 0; k < KC; k++) s += base[k * RWIN];
        if (a == 0) sQ2[r] = s; else sA[r] = s;
    }
    __syncthreads();  // Sp consumed; region reused as Cp next

    // ---- C: write partials, reduce over kc -> Xs band -------------------
    if (act) {
        #pragma unroll
        for (int tt = 0; tt < 4; tt++)
            #pragma unroll
            for (int m = 0; m < 4; m++)
                Cp[kc * TI * RWIN + (tg * 4 + tt) * RWIN + (rq + 33 * m)] = acc[tt][m];
    }
    __syncthreads();
    for (int o = tid; o < TI * RWIN; o += NTHREADS) {
        int t = o / RWIN;
        int r = o - t * RWIN;
        const float* base = Cp + t * RWIN + r;
        float x = 0.f;
        #pragma unroll
        for (int k = 0; k < KC; k++) x += base[k * TI * RWIN];
        int kk = t + 122 - r;          // k + 61
        if ((unsigned)kk < (unsigned)NK) Xs[t][kk] = x;
    }
    __syncthreads();

    // ---- Phase 3: evaluate 240 steps over this block's 8 bins -----------
    if (tid < NSTEPS) {
        const int s = tid;
        int k0, k1; float alpha; bool pos;
        if (s < 120) {                         // steps 0.0, 0.5, ..., 59.5
            k0 = s >> 1; k1 = k0 + 1;
            alpha = (s & 1) ? 0.5f : 0.0f;
            pos = true;
        } else {                               // steps -1.0, -1.5, ..., -60.5
            int u = s - 120;
            k0 = -(1 + (u >> 1)); k1 = k0 - 1;
            alpha = (u & 1) ? 0.5f : 0.0f;
            pos = false;
        }
        const float w0 = 1.0f - alpha, w1 = alpha;
        const float w00 = w0 * w0, w11 = w1 * w1, w01 = 2.0f * w0 * w1;
        float accs = 0.0f;
        #pragma unroll
        for (int t = 0; t < TI; t++) {
            int j0r = t + 61 - k0;             // window-relative row of roll k0
            int j1r = t + 61 - k1;
            float adot = pos ? sA[j0r] : sA[j1r];   // Q[j0].Q[j1] adjacency
            float x0 = Xs[t][k0 + 61];
            float x1 = Xs[t][k1 + 61];
            float r2 = sP2[t] + w00 * sQ2[j0r] + w11 * sQ2[j1r]
                     + w01 * adot - 2.0f * (w0 * x0 + w1 * x1);
            accs += sqrtf(fmaxf(r2, 0.0f));
        }
        g_bpart[s * NBLK + blockIdx.x] = accs;
    }

    // ---- Phase 4: last block reduces everything (no second launch) ------
    __threadfence();
    __syncthreads();                 // all phase-3 stores of this block issued
    if (tid == 0) {
        unsigned t = atomicAdd(&g_ticket, 1u);
        is_last = (t == (unsigned)(NBLK - 1));
        if (is_last) g_ticket = 0;   // reset for next graph replay
    }
    __syncthreads();
    if (!is_last) return;

    // Deterministic mean + argmin (identical summation order every launch).
    const int s    = tid >> 1;       // 2 threads per step, 64 partials each
    const int half = tid & 1;
    unsigned long long key = ~0ull;
    if (s < NSTEPS) {
        const float4* bp = (const float4*)(g_bpart + s * NBLK + half * (NBLK / 2));
        float s0 = 0.f, s1 = 0.f, s2 = 0.f, s3 = 0.f;
        #pragma unroll
        for (int c = 0; c < NBLK / 8; c += 4) {
            float4 v0 = bp[c], v1 = bp[c + 1], v2 = bp[c + 2], v3 = bp[c + 3];
            s0 += v0.x + v0.y + v0.z + v0.w;
            s1 += v1.x + v1.y + v1.z + v1.w;
            s2 += v2.x + v2.y + v2.z + v2.w;
            s3 += v3.x + v3.y + v3.z + v3.w;
        }
        float mine = (s0 + s1) + (s2 + s3);
        float tot  = mine + __shfl_xor_sync(0xffffffffu, mine, 1);
        float dist = tot * (1.0f / (float)N_BINS);
        // positive-float bit order == numeric order; low 32 bits = index so
        // ties resolve to the smallest step index (matches jnp.argmin).
        key = ((unsigned long long)__float_as_uint(dist) << 32) | (unsigned)s;
    }
    #pragma unroll
    for (int off = 16; off; off >>= 1) {
        unsigned long long o = __shfl_xor_sync(0xffffffffu, key, off);
        if (o < key) key = o;
    }
    if (lane == 0) wk[warp] = key;
    __syncthreads();
    if (tid == 0) {
        unsigned long long best = wk[0];
        #pragma unroll
        for (int w = 1; w < NTHREADS / 32; w++) if (wk[w] < best) best = wk[w];
        int bi = (int)(best & 0xffffffffull);
        float dist = __uint_as_float((unsigned)(best >> 32));
        float step = (bi < 120) ? 0.5f * (float)bi : -(1.0f + 0.5f * (float)(bi - 120));
        out[0] = step;
        out[1] = dist;
    }
}

extern "C" void kernel_launch(void* const* d_in, const int* in_sizes, int n_in,
                              void* d_out, int out_size) {
    const float* Dq = (const float*)d_in[0];  // D_q [1024, 512]
    const float* Dp = (const float*)d_in[1];  // D_p [1024, 512]
    float* out = (float*)d_out;

    k_main<<<NBLK, NTHREADS>>>(Dq, Dp, out);
}